// round 1
// baseline (speedup 1.0000x reference)
#include <cuda_runtime.h>

// Problem constants
#define BB   1024
#define NN   64
#define CDIM 256
#define HH   8
#define OO   64

// smem padding
#define XPAD  260   // x row stride (floats)
#define QPAD  68    // q/k/v/scores/adj row stride
#define WTPAD 196   // staged-W row stride (indexed [kk][col])

// smem layout (floats)
#define OFF_XS   0
#define OFF_WT   (OFF_XS + 64*XPAD)          // 16640
#define OFF_QS   (OFF_WT + 32*WTPAD)         // +6272
#define OFF_KS   (OFF_QS + 64*QPAD)
#define OFF_VS   (OFF_KS + 64*QPAD)
#define OFF_SS   (OFF_VS + 64*QPAD)
#define OFF_AD   (OFF_SS + 64*QPAD)
#define OFF_EC   (OFF_AD + 64*QPAD)
#define OFF_QE   (OFF_EC + 64)
#define OFF_EW   (OFF_QE + 64)
#define SMEM_FLOATS (OFF_EW + 64)            // 44864 floats = 179456 bytes

__global__ __launch_bounds__(256, 1)
void graphlearner_kernel(const float* __restrict__ ctx, const float* __restrict__ adj,
                         const float* __restrict__ Wq, const float* __restrict__ bq,
                         const float* __restrict__ Wk, const float* __restrict__ bk,
                         const float* __restrict__ Wv, const float* __restrict__ bv,
                         const float* __restrict__ We, const float* __restrict__ Ws,
                         const float* __restrict__ bs, float* __restrict__ out)
{
    extern __shared__ float sm[];
    float* xs  = sm + OFF_XS;   // [64][XPAD]
    float* wt  = sm + OFF_WT;   // [32][WTPAD]  staged weights, [kk][col]
    float* qs  = sm + OFF_QS;   // [64][QPAD]
    float* ks  = sm + OFF_KS;
    float* vs  = sm + OFF_VS;
    float* ss  = sm + OFF_SS;   // scores -> alpha
    float* ad  = sm + OFF_AD;   // adjT: ad[i][j] = adj[b][j][i]
    float* ec  = sm + OFF_EC;   // [64] ecoef per row
    float* qe  = sm + OFF_QE;   // [64] q_i . ew
    float* ews = sm + OFF_EW;   // [64] edge weight this head

    const int b  = blockIdx.x;
    const int t  = threadIdx.x;
    const int tx = t & 15;
    const int ty = t >> 4;
    const int i0 = ty * 4;      // row tile base (i)

    // ---- load x_b into smem (float4, coalesced) ----
    {
        const float4* xg = (const float4*)(ctx + (size_t)b * (NN * CDIM));
        for (int l = t; l < NN * CDIM / 4; l += 256) {
            int e = l * 4;
            int i = e / CDIM;
            int k = e % CDIM;
            float4 v4 = xg[l];
            float* d = &xs[i * XPAD + k];
            d[0] = v4.x; d[1] = v4.y; d[2] = v4.z; d[3] = v4.w;
        }
    }
    // ---- load adjT ----
    {
        const float* ag = adj + (size_t)b * (NN * NN);
        for (int l = t; l < NN * NN; l += 256) {
            int j = l >> 6, i = l & 63;
            ad[i * QPAD + j] = ag[l];   // ad[i][j] = adj[b][j][i]
        }
    }

    // persistent attention-out accumulator: thread owns i in [i0,i0+4), o in [o0,o0+4)
    const int o0 = tx * 4;
    float outr[4][4];
#pragma unroll
    for (int r = 0; r < 4; r++)
#pragma unroll
        for (int c = 0; c < 4; c++) outr[r][c] = 0.f;

    for (int h = 0; h < HH; ++h) {
        if (t < 64) ews[t] = We[h * 64 + t];

        // ================= QKV projection GEMM =================
        // out[64 rows i][192 cols] ; col = m*64+o  (m: 0=q,1=k,2=v)
        float acc[4][12];
#pragma unroll
        for (int r = 0; r < 4; r++)
#pragma unroll
            for (int c = 0; c < 12; c++) acc[r][c] = 0.f;

        for (int k0 = 0; k0 < CDIM; k0 += 32) {
            __syncthreads();  // wt reuse safe; also covers xs/ews on first iter
            // stage: wt[kk][col] = Wm[(h*64+o)*256 + k0+kk]
            for (int l = t; l < 192 * 32; l += 256) {
                int kk  = l & 31;
                int col = l >> 5;
                int m = col >> 6, o = col & 63;
                const float* Wm = (m == 0) ? Wq : (m == 1) ? Wk : Wv;
                wt[kk * WTPAD + col] = Wm[(h * 64 + o) * CDIM + k0 + kk];
            }
            __syncthreads();
#pragma unroll
            for (int kk = 0; kk < 32; kk += 4) {
                float4 a4[4];
#pragma unroll
                for (int r = 0; r < 4; r++)
                    a4[r] = *(const float4*)&xs[(i0 + r) * XPAD + k0 + kk];
#pragma unroll
                for (int u = 0; u < 4; u++) {
                    const float* wrow = &wt[(kk + u) * WTPAD + tx * 12];
                    float4 b0 = *(const float4*)&wrow[0];
                    float4 b1 = *(const float4*)&wrow[4];
                    float4 b2 = *(const float4*)&wrow[8];
                    float bvv[12] = {b0.x,b0.y,b0.z,b0.w, b1.x,b1.y,b1.z,b1.w,
                                     b2.x,b2.y,b2.z,b2.w};
#pragma unroll
                    for (int r = 0; r < 4; r++) {
                        float av = ((const float*)&a4[r])[u];
#pragma unroll
                        for (int c = 0; c < 12; c++)
                            acc[r][c] += av * bvv[c];
                    }
                }
            }
        }
        __syncthreads();
        // write q/k/v (+bias) to smem
#pragma unroll
        for (int c = 0; c < 12; c++) {
            int col = tx * 12 + c;
            int m = col >> 6, o = col & 63;
            const float* bm = (m == 0) ? bq : (m == 1) ? bk : bv;
            float* dst = (m == 0) ? qs : (m == 1) ? ks : vs;
            float bias = bm[h * 64 + o];
#pragma unroll
            for (int r = 0; r < 4; r++)
                dst[(i0 + r) * QPAD + o] = acc[r][c] + bias;
        }
        __syncthreads();

        // ================= qe[i] = q_i . ew =================
        {
            int i = t >> 2, qtr = t & 3;
            const float* qrow = &qs[i * QPAD + qtr * 16];
            const float* erow = &ews[qtr * 16];
            float p = 0.f;
#pragma unroll
            for (int u = 0; u < 16; u++) p += qrow[u] * erow[u];
            p += __shfl_xor_sync(0xffffffffu, p, 1);
            p += __shfl_xor_sync(0xffffffffu, p, 2);
            if (qtr == 0) qe[i] = p;
        }
        __syncthreads();

        // ================= scores S = (q k^T + adjT*qe) / 8 =================
        {
            const int j0 = tx * 4;
            float sa[4][4];
#pragma unroll
            for (int r = 0; r < 4; r++)
#pragma unroll
                for (int c = 0; c < 4; c++) sa[r][c] = 0.f;
#pragma unroll
            for (int o = 0; o < 64; o += 4) {
                float4 aq[4], bk4[4];
#pragma unroll
                for (int r = 0; r < 4; r++) aq[r]  = *(const float4*)&qs[(i0 + r) * QPAD + o];
#pragma unroll
                for (int c = 0; c < 4; c++) bk4[c] = *(const float4*)&ks[(j0 + c) * QPAD + o];
#pragma unroll
                for (int r = 0; r < 4; r++)
#pragma unroll
                    for (int c = 0; c < 4; c++)
                        sa[r][c] += aq[r].x * bk4[c].x + aq[r].y * bk4[c].y
                                  + aq[r].z * bk4[c].z + aq[r].w * bk4[c].w;
            }
#pragma unroll
            for (int r = 0; r < 4; r++) {
                float qei = qe[i0 + r];
#pragma unroll
                for (int c = 0; c < 4; c++)
                    ss[(i0 + r) * QPAD + j0 + c] =
                        0.125f * (sa[r][c] + ad[(i0 + r) * QPAD + j0 + c] * qei);
            }
        }
        __syncthreads();

        // ================= softmax over j (4 threads / row) + ecoef =================
        {
            int i = t >> 2, qtr = t & 3;
            float* row = &ss[i * QPAD + qtr * 16];
            const float* arow = &ad[i * QPAD + qtr * 16];
            float m = -1e30f;
#pragma unroll
            for (int u = 0; u < 16; u++) m = fmaxf(m, row[u]);
            m = fmaxf(m, __shfl_xor_sync(0xffffffffu, m, 1));
            m = fmaxf(m, __shfl_xor_sync(0xffffffffu, m, 2));
            float e[16];
            float s = 0.f;
#pragma unroll
            for (int u = 0; u < 16; u++) { e[u] = __expf(row[u] - m); s += e[u]; }
            s += __shfl_xor_sync(0xffffffffu, s, 1);
            s += __shfl_xor_sync(0xffffffffu, s, 2);
            float rinv = 1.f / s;
            float pc = 0.f;
#pragma unroll
            for (int u = 0; u < 16; u++) {
                float al = e[u] * rinv;
                row[u] = al;
                pc += al * arow[u];
            }
            pc += __shfl_xor_sync(0xffffffffu, pc, 1);
            pc += __shfl_xor_sync(0xffffffffu, pc, 2);
            if (qtr == 0) ec[i] = pc;
        }
        __syncthreads();

        // ================= out += alpha @ v  +  ec_i * ew_o =================
        {
            float sa[4][4];
#pragma unroll
            for (int r = 0; r < 4; r++)
#pragma unroll
                for (int c = 0; c < 4; c++) sa[r][c] = 0.f;
#pragma unroll 8
            for (int j = 0; j < 64; j++) {
                float4 bv4 = *(const float4*)&vs[j * QPAD + o0];
#pragma unroll
                for (int r = 0; r < 4; r++) {
                    float al = ss[(i0 + r) * QPAD + j];
                    sa[r][0] += al * bv4.x;
                    sa[r][1] += al * bv4.y;
                    sa[r][2] += al * bv4.z;
                    sa[r][3] += al * bv4.w;
                }
            }
#pragma unroll
            for (int r = 0; r < 4; r++) {
                float eci = ec[i0 + r];
#pragma unroll
                for (int c = 0; c < 4; c++)
                    outr[r][c] += sa[r][c] + eci * ews[o0 + c];
            }
        }
        __syncthreads();  // before next head overwrites qs/ks/vs/ss/ews
    }

    // ================= skip GEMM: sk = x @ Ws^T =================
    float sk[4][4];
#pragma unroll
    for (int r = 0; r < 4; r++)
#pragma unroll
        for (int c = 0; c < 4; c++) sk[r][c] = 0.f;

    for (int k0 = 0; k0 < CDIM; k0 += 32) {
        __syncthreads();
        for (int l = t; l < 64 * 32; l += 256) {
            int kk = l & 31, o = l >> 5;
            wt[kk * WTPAD + o] = Ws[o * CDIM + k0 + kk];
        }
        __syncthreads();
#pragma unroll
        for (int kk = 0; kk < 32; kk += 4) {
            float4 a4[4];
#pragma unroll
            for (int r = 0; r < 4; r++)
                a4[r] = *(const float4*)&xs[(i0 + r) * XPAD + k0 + kk];
#pragma unroll
            for (int u = 0; u < 4; u++) {
                float4 b4 = *(const float4*)&wt[(kk + u) * WTPAD + o0];
#pragma unroll
                for (int r = 0; r < 4; r++) {
                    float av = ((const float*)&a4[r])[u];
                    sk[r][0] += av * b4.x;
                    sk[r][1] += av * b4.y;
                    sk[r][2] += av * b4.z;
                    sk[r][3] += av * b4.w;
                }
            }
        }
    }

    // ================= epilogue: mean heads + skip + bias, threshold, sigmoid =================
    {
        float4* og = (float4*)(out + (size_t)b * (NN * OO));
#pragma unroll
        for (int r = 0; r < 4; r++) {
            float4 res;
            float v0 = outr[r][0] * 0.125f + sk[r][0] + bs[o0 + 0];
            float v1 = outr[r][1] * 0.125f + sk[r][1] + bs[o0 + 1];
            float v2 = outr[r][2] * 0.125f + sk[r][2] + bs[o0 + 2];
            float v3 = outr[r][3] * 0.125f + sk[r][3] + bs[o0 + 3];
            res.x = (v0 > 0.1f) ? 1.f / (1.f + __expf(-v0)) : 0.f;
            res.y = (v1 > 0.1f) ? 1.f / (1.f + __expf(-v1)) : 0.f;
            res.z = (v2 > 0.1f) ? 1.f / (1.f + __expf(-v2)) : 0.f;
            res.w = (v3 > 0.1f) ? 1.f / (1.f + __expf(-v3)) : 0.f;
            og[(i0 + r) * 16 + tx] = res;
        }
    }
}

extern "C" void kernel_launch(void* const* d_in, const int* in_sizes, int n_in,
                              void* d_out, int out_size)
{
    const float* ctx = (const float*)d_in[0];
    const float* adj = (const float*)d_in[1];
    const float* Wq  = (const float*)d_in[2];
    const float* bq  = (const float*)d_in[3];
    const float* Wk  = (const float*)d_in[4];
    const float* bk  = (const float*)d_in[5];
    const float* Wv  = (const float*)d_in[6];
    const float* bv  = (const float*)d_in[7];
    const float* We  = (const float*)d_in[8];
    const float* Ws  = (const float*)d_in[9];
    const float* bs  = (const float*)d_in[10];
    float* out = (float*)d_out;

    const int smem_bytes = SMEM_FLOATS * sizeof(float);
    cudaFuncSetAttribute(graphlearner_kernel,
                         cudaFuncAttributeMaxDynamicSharedMemorySize, smem_bytes);
    graphlearner_kernel<<<BB, 256, smem_bytes>>>(ctx, adj, Wq, bq, Wk, bk, Wv, bv,
                                                 We, Ws, bs, out);
}

// round 3
// speedup vs baseline: 1.1503x; 1.1503x over previous
#include <cuda_runtime.h>

// Problem constants
#define BB   1024
#define NN   64
#define CDIM 256
#define HH   8
#define OO   64
#define THREADS 512

// smem padding
#define XPAD  260   // x row stride (floats)
#define QPAD  68    // q/k/v/scores/adj row stride
#define WTPAD 196   // staged-W row stride (indexed [kk][col])

// smem layout (floats)
#define OFF_XS   0
#define OFF_WT0  (OFF_XS + 64*XPAD)           // 16640
#define OFF_WT1  (OFF_WT0 + 32*WTPAD)         // +6272
#define OFF_QS   (OFF_WT1 + 32*WTPAD)         // 29184
#define OFF_KS   (OFF_QS + 64*QPAD)
#define OFF_VS   (OFF_KS + 64*QPAD)
#define OFF_SS   (OFF_VS + 64*QPAD)
#define OFF_AD   (OFF_SS + 64*QPAD)
#define OFF_EC   (OFF_AD + 64*QPAD)           // 50944
#define OFF_QE   (OFF_EC + 64)
#define OFF_EW   (OFF_QE + 64)
#define SMEM_FLOATS (OFF_EW + 64)             // 51136 floats = 204544 bytes

__global__ __launch_bounds__(THREADS, 1)
void graphlearner_kernel(const float* __restrict__ ctx, const float* __restrict__ adj,
                         const float* __restrict__ Wq, const float* __restrict__ bq,
                         const float* __restrict__ Wk, const float* __restrict__ bk,
                         const float* __restrict__ Wv, const float* __restrict__ bv,
                         const float* __restrict__ We, const float* __restrict__ Ws,
                         const float* __restrict__ bs, float* __restrict__ out)
{
    extern __shared__ float sm[];
    float* xs   = sm + OFF_XS;   // [64][XPAD]
    float* wt0  = sm + OFF_WT0;  // staged weights buffer 0
    float* wt1  = sm + OFF_WT1;  // staged weights buffer 1
    float* qs   = sm + OFF_QS;
    float* ks   = sm + OFF_KS;
    float* vs   = sm + OFF_VS;
    float* ss   = sm + OFF_SS;   // scores -> alpha
    float* ad   = sm + OFF_AD;   // adjT: ad[i][j] = adj[b][j][i]
    float* ec   = sm + OFF_EC;
    float* qe   = sm + OFF_QE;
    float* ews  = sm + OFF_EW;

    const int b = blockIdx.x;
    const int t = threadIdx.x;

    // GEMM mapping: 16 row-groups x 32 col-groups (4 rows x 6 cols per thread)
    const int txg = t & 31;
    const int tyg = t >> 5;        // warp id: each warp owns one 4-row group
    const int i0g = tyg * 4;
    const int c0  = txg * 6;

    // 2x4 mapping for scores/AV/skip/epilogue
    const int tx8 = t & 15;
    const int ty8 = t >> 4;        // 0..31
    const int i02 = ty8 * 2;
    const int o0  = tx8 * 4;

    // 8-threads-per-row mapping (qe / softmax)
    const int rw  = t >> 3;        // row 0..63
    const int oct = t & 7;

    // ---- load x_b (float4, coalesced) ----
    {
        const float4* xg = (const float4*)(ctx + (size_t)b * (NN * CDIM));
        for (int l = t; l < NN * CDIM / 4; l += THREADS) {
            int e = l * 4;
            int i = e >> 8;
            int k = e & 255;
            float4 v4 = xg[l];
            float* d = &xs[i * XPAD + k];
            d[0] = v4.x; d[1] = v4.y; d[2] = v4.z; d[3] = v4.w;
        }
    }
    // ---- load adjT ----
    {
        const float* ag = adj + (size_t)b * (NN * NN);
        for (int l = t; l < NN * NN; l += THREADS) {
            int j = l >> 6, i = l & 63;
            ad[i * QPAD + j] = ag[l];
        }
    }

    // persistent attention-out accumulator (2 rows x 4 cols)
    float outr[2][4];
#pragma unroll
    for (int r = 0; r < 2; r++)
#pragma unroll
        for (int c = 0; c < 4; c++) outr[r][c] = 0.f;

    for (int h = 0; h < HH; ++h) {
        if (t < 64) ews[t] = We[h * 64 + t];

        // ================= QKV projection GEMM (64x192x256) =================
        float acc[4][6];
#pragma unroll
        for (int r = 0; r < 4; r++)
#pragma unroll
            for (int c = 0; c < 6; c++) acc[r][c] = 0.f;

        // stage chunk k0 into buf: buf[kk][col] = Wm[(h*64+o)*256 + k0+kk]
        const int hbase = h * 64;
        {
            // prologue stage into wt0 (k0 = 0)
            for (int l = t; l < 192 * 32; l += THREADS) {
                int kk = l & 31, col = l >> 5;
                int m = col >> 6, o = col & 63;
                const float* Wm = (m == 0) ? Wq : (m == 1) ? Wk : Wv;
                wt0[kk * WTPAD + col] = Wm[(hbase + o) * CDIM + kk];
            }
        }
        __syncthreads();

        for (int kb = 0; kb < 8; kb++) {
            const int k0 = kb * 32;
            float* cur = (kb & 1) ? wt1 : wt0;
            float* nxt = (kb & 1) ? wt0 : wt1;
            if (kb < 7) {
                const int kn = k0 + 32;
                for (int l = t; l < 192 * 32; l += THREADS) {
                    int kk = l & 31, col = l >> 5;
                    int m = col >> 6, o = col & 63;
                    const float* Wm = (m == 0) ? Wq : (m == 1) ? Wk : Wv;
                    nxt[kk * WTPAD + col] = Wm[(hbase + o) * CDIM + kn + kk];
                }
            }
#pragma unroll
            for (int kk = 0; kk < 32; kk += 4) {
                float4 a4[4];
#pragma unroll
                for (int r = 0; r < 4; r++)
                    a4[r] = *(const float4*)&xs[(i0g + r) * XPAD + k0 + kk];
#pragma unroll
                for (int u = 0; u < 4; u++) {
                    const float* wrow = &cur[(kk + u) * WTPAD + c0];
                    float2 b0 = *(const float2*)(wrow);
                    float2 b1 = *(const float2*)(wrow + 2);
                    float2 b2 = *(const float2*)(wrow + 4);
#pragma unroll
                    for (int r = 0; r < 4; r++) {
                        float av = ((const float*)&a4[r])[u];
                        acc[r][0] += av * b0.x;
                        acc[r][1] += av * b0.y;
                        acc[r][2] += av * b1.x;
                        acc[r][3] += av * b1.y;
                        acc[r][4] += av * b2.x;
                        acc[r][5] += av * b2.y;
                    }
                }
            }
            __syncthreads();
        }

        // write q/k/v (+bias) to smem
#pragma unroll
        for (int c = 0; c < 6; c++) {
            int col = c0 + c;
            int m = col >> 6, o = col & 63;
            const float* bm = (m == 0) ? bq : (m == 1) ? bk : bv;
            float* dst = (m == 0) ? qs : (m == 1) ? ks : vs;
            float bias = bm[hbase + o];
#pragma unroll
            for (int r = 0; r < 4; r++)
                dst[(i0g + r) * QPAD + o] = acc[r][c] + bias;
        }
        __syncthreads();

        // ================= qe[i] = q_i . ew (8 threads/row) =================
        {
            const float* qrow = &qs[rw * QPAD + oct * 8];
            const float* erow = &ews[oct * 8];
            float p = 0.f;
#pragma unroll
            for (int u = 0; u < 8; u++) p += qrow[u] * erow[u];
            p += __shfl_xor_sync(0xffffffffu, p, 1);
            p += __shfl_xor_sync(0xffffffffu, p, 2);
            p += __shfl_xor_sync(0xffffffffu, p, 4);
            if (oct == 0) qe[rw] = p;
        }
        __syncthreads();

        // ================= scores S = (q k^T + adjT*qe)/8 (2x4 tile) =================
        {
            float sa[2][4];
#pragma unroll
            for (int r = 0; r < 2; r++)
#pragma unroll
                for (int c = 0; c < 4; c++) sa[r][c] = 0.f;
#pragma unroll
            for (int o = 0; o < 64; o += 4) {
                float4 aq[2], bk4[4];
#pragma unroll
                for (int r = 0; r < 2; r++) aq[r]  = *(const float4*)&qs[(i02 + r) * QPAD + o];
#pragma unroll
                for (int c = 0; c < 4; c++) bk4[c] = *(const float4*)&ks[(o0 + c) * QPAD + o];
#pragma unroll
                for (int r = 0; r < 2; r++)
#pragma unroll
                    for (int c = 0; c < 4; c++)
                        sa[r][c] += aq[r].x * bk4[c].x + aq[r].y * bk4[c].y
                                  + aq[r].z * bk4[c].z + aq[r].w * bk4[c].w;
            }
#pragma unroll
            for (int r = 0; r < 2; r++) {
                float qei = qe[i02 + r];
#pragma unroll
                for (int c = 0; c < 4; c++)
                    ss[(i02 + r) * QPAD + o0 + c] =
                        0.125f * (sa[r][c] + ad[(i02 + r) * QPAD + o0 + c] * qei);
            }
        }
        __syncthreads();

        // ================= softmax over j (8 threads/row) + ecoef =================
        {
            float* row = &ss[rw * QPAD + oct * 8];
            const float* arow = &ad[rw * QPAD + oct * 8];
            float m = -1e30f;
#pragma unroll
            for (int u = 0; u < 8; u++) m = fmaxf(m, row[u]);
            m = fmaxf(m, __shfl_xor_sync(0xffffffffu, m, 1));
            m = fmaxf(m, __shfl_xor_sync(0xffffffffu, m, 2));
            m = fmaxf(m, __shfl_xor_sync(0xffffffffu, m, 4));
            float e[8];
            float s = 0.f;
#pragma unroll
            for (int u = 0; u < 8; u++) { e[u] = __expf(row[u] - m); s += e[u]; }
            s += __shfl_xor_sync(0xffffffffu, s, 1);
            s += __shfl_xor_sync(0xffffffffu, s, 2);
            s += __shfl_xor_sync(0xffffffffu, s, 4);
            float rinv = 1.f / s;
            float pc = 0.f;
#pragma unroll
            for (int u = 0; u < 8; u++) {
                float al = e[u] * rinv;
                row[u] = al;
                pc += al * arow[u];
            }
            pc += __shfl_xor_sync(0xffffffffu, pc, 1);
            pc += __shfl_xor_sync(0xffffffffu, pc, 2);
            pc += __shfl_xor_sync(0xffffffffu, pc, 4);
            if (oct == 0) ec[rw] = pc;
        }
        __syncthreads();

        // ================= out += alpha @ v  +  ec_i * ew_o =================
        {
            float sa[2][4];
#pragma unroll
            for (int r = 0; r < 2; r++)
#pragma unroll
                for (int c = 0; c < 4; c++) sa[r][c] = 0.f;
#pragma unroll 8
            for (int j = 0; j < 64; j++) {
                float4 bv4 = *(const float4*)&vs[j * QPAD + o0];
#pragma unroll
                for (int r = 0; r < 2; r++) {
                    float al = ss[(i02 + r) * QPAD + j];
                    sa[r][0] += al * bv4.x;
                    sa[r][1] += al * bv4.y;
                    sa[r][2] += al * bv4.z;
                    sa[r][3] += al * bv4.w;
                }
            }
#pragma unroll
            for (int r = 0; r < 2; r++) {
                float eci = ec[i02 + r];
#pragma unroll
                for (int c = 0; c < 4; c++)
                    outr[r][c] += sa[r][c] + eci * ews[o0 + c];
            }
        }
        __syncthreads();  // before next head overwrites qs/ks/vs/ss/ews
    }

    // ================= skip GEMM: sk = x @ Ws^T (2x4 tile, ping-pong) =================
    float sk[2][4];
#pragma unroll
    for (int r = 0; r < 2; r++)
#pragma unroll
        for (int c = 0; c < 4; c++) sk[r][c] = 0.f;

    for (int l = t; l < 64 * 32; l += THREADS) {
        int kk = l & 31, o = l >> 5;
        wt0[kk * WTPAD + o] = Ws[o * CDIM + kk];
    }
    __syncthreads();

    for (int kb = 0; kb < 8; kb++) {
        const int k0 = kb * 32;
        float* cur = (kb & 1) ? wt1 : wt0;
        float* nxt = (kb & 1) ? wt0 : wt1;
        if (kb < 7) {
            const int kn = k0 + 32;
            for (int l = t; l < 64 * 32; l += THREADS) {
                int kk = l & 31, o = l >> 5;
                nxt[kk * WTPAD + o] = Ws[o * CDIM + kn + kk];
            }
        }
#pragma unroll
        for (int kk = 0; kk < 32; kk += 4) {
            float4 a4[2];
#pragma unroll
            for (int r = 0; r < 2; r++)
                a4[r] = *(const float4*)&xs[(i02 + r) * XPAD + k0 + kk];
#pragma unroll
            for (int u = 0; u < 4; u++) {
                float4 b4 = *(const float4*)&cur[(kk + u) * WTPAD + o0];
#pragma unroll
                for (int r = 0; r < 2; r++) {
                    float av = ((const float*)&a4[r])[u];
                    sk[r][0] += av * b4.x;
                    sk[r][1] += av * b4.y;
                    sk[r][2] += av * b4.z;
                    sk[r][3] += av * b4.w;
                }
            }
        }
        __syncthreads();
    }

    // ================= epilogue =================
    {
        float4* og = (float4*)(out + (size_t)b * (NN * OO));
#pragma unroll
        for (int r = 0; r < 2; r++) {
            float4 res;
            float v0 = outr[r][0] * 0.125f + sk[r][0] + bs[o0 + 0];
            float v1 = outr[r][1] * 0.125f + sk[r][1] + bs[o0 + 1];
            float v2 = outr[r][2] * 0.125f + sk[r][2] + bs[o0 + 2];
            float v3 = outr[r][3] * 0.125f + sk[r][3] + bs[o0 + 3];
            res.x = (v0 > 0.1f) ? 1.f / (1.f + __expf(-v0)) : 0.f;
            res.y = (v1 > 0.1f) ? 1.f / (1.f + __expf(-v1)) : 0.f;
            res.z = (v2 > 0.1f) ? 1.f / (1.f + __expf(-v2)) : 0.f;
            res.w = (v3 > 0.1f) ? 1.f / (1.f + __expf(-v3)) : 0.f;
            og[(i02 + r) * 16 + tx8] = res;
        }
    }
}

extern "C" void kernel_launch(void* const* d_in, const int* in_sizes, int n_in,
                              void* d_out, int out_size)
{
    const float* ctx = (const float*)d_in[0];
    const float* adj = (const float*)d_in[1];
    const float* Wq  = (const float*)d_in[2];
    const float* bq  = (const float*)d_in[3];
    const float* Wk  = (const float*)d_in[4];
    const float* bk  = (const float*)d_in[5];
    const float* Wv  = (const float*)d_in[6];
    const float* bv  = (const float*)d_in[7];
    const float* We  = (const float*)d_in[8];
    const float* Ws  = (const float*)d_in[9];
    const float* bs  = (const float*)d_in[10];
    float* out = (float*)d_out;

    const int smem_bytes = SMEM_FLOATS * sizeof(float);
    cudaFuncSetAttribute(graphlearner_kernel,
                         cudaFuncAttributeMaxDynamicSharedMemorySize, smem_bytes);
    graphlearner_kernel<<<BB, THREADS, smem_bytes>>>(ctx, adj, Wq, bq, Wk, bk, Wv, bv,
                                                     We, Ws, bs, out);
}